// round 1
// baseline (speedup 1.0000x reference)
#include <cuda_runtime.h>
#include <math.h>

#define NODE   128
#define EDGED  64
#define INDIM  320
#define HID    128
#define EB     64
#define KC     16
#define PA     66
#define LN_EPS 1e-5f

// shared memory layout (float offsets)
#define SA_OFF 0
#define SA_SZ  (INDIM * PA)              // 21120 floats
#define SW_OFF SA_SZ
#define SW_BUF 4096                       // one buffer: 16 x 256 floats
#define SH_OFF (SW_OFF + 2 * SW_BUF)      // 29312
#define SH_SZ  (HID * EB)                 // 8192
#define SMEM_FLOATS (SH_OFF + SH_SZ)      // 37504 floats = 150016 B

__device__ __forceinline__ void ffma2(unsigned long long &d,
                                      unsigned long long a,
                                      unsigned long long b) {
    asm("fma.rn.f32x2 %0, %1, %2, %0;" : "+l"(d) : "l"(a), "l"(b));
}
__device__ __forceinline__ unsigned long long pk(float x, float y) {
    unsigned long long r;
    asm("mov.b64 %0, {%1, %2};" : "=l"(r) : "f"(x), "f"(y));
    return r;
}
__device__ __forceinline__ void upk(unsigned long long v, float &x, float &y) {
    asm("mov.b64 {%0, %1}, %2;" : "=f"(x), "=f"(y) : "l"(v));
}

__device__ __forceinline__ void load_chunk_w1g(const float* __restrict__ W1,
                                               const float* __restrict__ Wg,
                                               int c, int t, float4* r) {
#pragma unroll
    for (int i = 0; i < 4; i++) {
        int fl = t + 256 * i;
        int kk = fl >> 6;
        int n  = (fl & 63) << 2;
        const float* p = (n < HID) ? (W1 + (size_t)(c * KC + kk) * HID + n)
                                   : (Wg + (size_t)(c * KC + kk) * HID + (n - HID));
        r[i] = *(const float4*)p;
    }
}

__device__ __forceinline__ void load_chunk_n128(const float* __restrict__ W,
                                                int c, int t, float4* r) {
#pragma unroll
    for (int i = 0; i < 2; i++) {
        int fl = t + 256 * i;
        int kk = fl >> 5;
        int n  = (fl & 31) << 2;
        r[i] = *(const float4*)(W + (size_t)(c * KC + kk) * HID + n);
    }
}

__global__ __launch_bounds__(256, 1)
void edge_updater_kernel(const float* __restrict__ x,  const int* __restrict__ ei,
                         const float* __restrict__ ea,
                         const float* __restrict__ W1, const float* __restrict__ b1,
                         const float* __restrict__ g1, const float* __restrict__ be1,
                         const float* __restrict__ W2, const float* __restrict__ b2,
                         const float* __restrict__ Wg, const float* __restrict__ bg,
                         const float* __restrict__ Wr, const float* __restrict__ br,
                         const float* __restrict__ g2, const float* __restrict__ be2,
                         float* __restrict__ out, int E) {
    extern __shared__ float smem[];
    float* sA = smem + SA_OFF;   // [320][66] transposed cat_feat
    float* sW = smem + SW_OFF;   // double-buffered weight chunks
    float* sH = smem + SH_OFF;   // [128][64] h (transposed) for GEMM2

    const int t  = threadIdx.x;
    const int tx = t & 15;       // N-dim group
    const int ty = t >> 4;       // M-dim group (4 edges each)
    const int e0 = blockIdx.x * EB;

    // ---------------- gather cat_feat (transposed into sA) ----------------
    {
        const int warp = t >> 5, lane = t & 31;
        const int m  = warp * 8 + (lane & 7);
        const int fb = lane >> 3;
        const int e  = e0 + m;
        const bool valid = e < E;
        int src = 0, dst = 0;
        if (valid) { src = ei[e]; dst = ei[E + e]; }
        const float4* xs  = (const float4*)(x  + (size_t)src * NODE);
        const float4* xd  = (const float4*)(x  + (size_t)dst * NODE);
        const float4* eap = (const float4*)(ea + (size_t)e * EDGED);
#pragma unroll
        for (int f = fb; f < 80; f += 4) {
            float4 v = make_float4(0.f, 0.f, 0.f, 0.f);
            if (valid) {
                if (f < 32)      v = xs[f];
                else if (f < 64) v = xd[f - 32];
                else             v = eap[f - 64];
            }
            const int k = f * 4;
            sA[(k + 0) * PA + m] = v.x;
            sA[(k + 1) * PA + m] = v.y;
            sA[(k + 2) * PA + m] = v.z;
            sA[(k + 3) * PA + m] = v.w;
        }
    }

    // ---------------- GEMM1: cat[64,320] @ [W1|Wg][320,256] ----------------
    unsigned long long acc1[4][8];
#pragma unroll
    for (int m = 0; m < 4; m++)
#pragma unroll
        for (int p = 0; p < 8; p++) acc1[m][p] = 0ull;

    {
        float4 cur[4];
        load_chunk_w1g(W1, Wg, 0, t, cur);
#pragma unroll
        for (int i = 0; i < 4; i++) {
            int fl = t + 256 * i;
            *(float4*)(sW + fl * 4) = cur[i];
        }
    }
    __syncthreads();

    const int NCH1 = INDIM / KC; // 20
#pragma unroll 1
    for (int c = 0; c < NCH1; c++) {
        float4 nxt[4];
        if (c + 1 < NCH1) load_chunk_w1g(W1, Wg, c + 1, t, nxt);
        const float* wb = sW + (c & 1) * SW_BUF;
#pragma unroll
        for (int kk = 0; kk < KC; kk++) {
            const int k = c * KC + kk;
            const float* Ar = sA + k * PA + ty * 4;
            float2 a01 = *(const float2*)Ar;
            float2 a23 = *(const float2*)(Ar + 2);
            unsigned long long am[4];
            am[0] = pk(a01.x, a01.x); am[1] = pk(a01.y, a01.y);
            am[2] = pk(a23.x, a23.x); am[3] = pk(a23.y, a23.y);
            const double* Wd = (const double*)(wb + kk * 256);
            unsigned long long wp[8];
#pragma unroll
            for (int jv = 0; jv < 4; jv++) {
                double2 w2 = *(const double2*)(Wd + ((64 * jv + 4 * tx) >> 1));
                wp[2 * jv]     = __double_as_longlong(w2.x);
                wp[2 * jv + 1] = __double_as_longlong(w2.y);
            }
#pragma unroll
            for (int m = 0; m < 4; m++)
#pragma unroll
                for (int p = 0; p < 8; p++)
                    ffma2(acc1[m][p], am[m], wp[p]);
        }
        if (c + 1 < NCH1) {
            __syncthreads();
#pragma unroll
            for (int i = 0; i < 4; i++) {
                int fl = t + 256 * i;
                *(float4*)(sW + ((c + 1) & 1) * SW_BUF + fl * 4) = nxt[i];
            }
            __syncthreads();
        }
    }

    // ---------------- LN1 + GELU (-> sH), sigmoid gate (-> regs) ----------------
    float b1v[8], g1v[8], be1v[8], bgv[8];
#pragma unroll
    for (int j = 0; j < 8; j++) {
        int n = 64 * (j >> 2) + 4 * tx + (j & 3);
        b1v[j]  = __ldg(b1 + n);
        g1v[j]  = __ldg(g1 + n);
        be1v[j] = __ldg(be1 + n);
        bgv[j]  = __ldg(bg + n);
    }

    float gateR[4][8];
#pragma unroll
    for (int i = 0; i < 4; i++) {
        const int m = ty * 4 + i;
        float hv[8];
        float s = 0.f, sq = 0.f;
#pragma unroll
        for (int p = 0; p < 4; p++) {
            float a, b;
            upk(acc1[i][p], a, b);
            hv[2 * p]     = a + b1v[2 * p];
            hv[2 * p + 1] = b + b1v[2 * p + 1];
            s  += hv[2 * p] + hv[2 * p + 1];
            sq += hv[2 * p] * hv[2 * p] + hv[2 * p + 1] * hv[2 * p + 1];
        }
#pragma unroll
        for (int o = 1; o < 16; o <<= 1) {
            s  += __shfl_xor_sync(0xffffffffu, s, o);
            sq += __shfl_xor_sync(0xffffffffu, sq, o);
        }
        const float mu   = s * (1.f / 128.f);
        const float var  = sq * (1.f / 128.f) - mu * mu;
        const float rstd = rsqrtf(var + LN_EPS);
#pragma unroll
        for (int j = 0; j < 8; j++) {
            const int n = 64 * (j >> 2) + 4 * tx + (j & 3);
            float hn = (hv[j] - mu) * rstd * g1v[j] + be1v[j];
            float g  = 0.5f * hn * (1.f + erff(hn * 0.70710678118654752f));
            sH[n * EB + m] = g;
        }
#pragma unroll
        for (int p = 0; p < 4; p++) {
            float a, b;
            upk(acc1[i][4 + p], a, b);
            gateR[i][2 * p]     = 1.f / (1.f + __expf(-(a + bgv[2 * p])));
            gateR[i][2 * p + 1] = 1.f / (1.f + __expf(-(b + bgv[2 * p + 1])));
        }
    }
    __syncthreads(); // sH visible; GEMM1 fully drained

    // ---------------- GEMM2: h @ W2 and ea @ Wr ----------------
    unsigned long long aU[4][4], aR[4][4];
#pragma unroll
    for (int m = 0; m < 4; m++)
#pragma unroll
        for (int p = 0; p < 4; p++) { aU[m][p] = 0ull; aR[m][p] = 0ull; }

    {
        float4 r2[2];
        load_chunk_n128(W2, 0, t, r2);
#pragma unroll
        for (int i = 0; i < 2; i++) {
            int fl = t + 256 * i;
            *(float4*)(sW + fl * 4) = r2[i];
        }
    }
    __syncthreads();

#pragma unroll 1
    for (int c = 0; c < 8; c++) {
        float4 nxt[2];
        if (c + 1 < 8) load_chunk_n128(W2, c + 1, t, nxt);
        const float* wb = sW + (c & 1) * SW_BUF;
#pragma unroll
        for (int kk = 0; kk < KC; kk++) {
            const int k = c * KC + kk;
            float4 a4 = *(const float4*)(sH + k * EB + ty * 4);
            unsigned long long am[4] = {pk(a4.x, a4.x), pk(a4.y, a4.y),
                                        pk(a4.z, a4.z), pk(a4.w, a4.w)};
            const double* Wd = (const double*)(wb + kk * HID);
            unsigned long long wp[4];
#pragma unroll
            for (int jv = 0; jv < 2; jv++) {
                double2 w2 = *(const double2*)(Wd + ((64 * jv + 4 * tx) >> 1));
                wp[2 * jv]     = __double_as_longlong(w2.x);
                wp[2 * jv + 1] = __double_as_longlong(w2.y);
            }
#pragma unroll
            for (int m = 0; m < 4; m++)
#pragma unroll
                for (int p = 0; p < 4; p++)
                    ffma2(aU[m][p], am[m], wp[p]);
        }
        if (c + 1 < 8) {
            __syncthreads();
#pragma unroll
            for (int i = 0; i < 2; i++) {
                int fl = t + 256 * i;
                *(float4*)(sW + ((c + 1) & 1) * SW_BUF + fl * 4) = nxt[i];
            }
            __syncthreads();
        }
    }

    // res GEMM: ea (sA rows 256..319) @ Wr
    {
        float4 r2[2];
        load_chunk_n128(Wr, 0, t, r2);
        __syncthreads();
#pragma unroll
        for (int i = 0; i < 2; i++) {
            int fl = t + 256 * i;
            *(float4*)(sW + fl * 4) = r2[i];
        }
        __syncthreads();
    }
#pragma unroll 1
    for (int c = 0; c < 4; c++) {
        float4 nxt[2];
        if (c + 1 < 4) load_chunk_n128(Wr, c + 1, t, nxt);
        const float* wb = sW + (c & 1) * SW_BUF;
#pragma unroll
        for (int kk = 0; kk < KC; kk++) {
            const int k = c * KC + kk;
            const float* Ar = sA + (256 + k) * PA + ty * 4;
            float2 a01 = *(const float2*)Ar;
            float2 a23 = *(const float2*)(Ar + 2);
            unsigned long long am[4] = {pk(a01.x, a01.x), pk(a01.y, a01.y),
                                        pk(a23.x, a23.x), pk(a23.y, a23.y)};
            const double* Wd = (const double*)(wb + kk * HID);
            unsigned long long wp[4];
#pragma unroll
            for (int jv = 0; jv < 2; jv++) {
                double2 w2 = *(const double2*)(Wd + ((64 * jv + 4 * tx) >> 1));
                wp[2 * jv]     = __double_as_longlong(w2.x);
                wp[2 * jv + 1] = __double_as_longlong(w2.y);
            }
#pragma unroll
            for (int m = 0; m < 4; m++)
#pragma unroll
                for (int p = 0; p < 4; p++)
                    ffma2(aR[m][p], am[m], wp[p]);
        }
        if (c + 1 < 4) {
            __syncthreads();
#pragma unroll
            for (int i = 0; i < 2; i++) {
                int fl = t + 256 * i;
                *(float4*)(sW + ((c + 1) & 1) * SW_BUF + fl * 4) = nxt[i];
            }
            __syncthreads();
        }
    }

    // ---------------- epilogue: gate * update + res, LN2, store ----------------
    float b2v[8], brv[8], g2v[8], be2v[8];
#pragma unroll
    for (int j = 0; j < 8; j++) {
        int n = 64 * (j >> 2) + 4 * tx + (j & 3);
        b2v[j]  = __ldg(b2 + n);
        brv[j]  = __ldg(br + n);
        g2v[j]  = __ldg(g2 + n);
        be2v[j] = __ldg(be2 + n);
    }

#pragma unroll
    for (int i = 0; i < 4; i++) {
        const int m = ty * 4 + i;
        const int e = e0 + m;
        float pv[8];
        float s = 0.f, sq = 0.f;
#pragma unroll
        for (int p = 0; p < 4; p++) {
            float u0, u1, r0, r1;
            upk(aU[i][p], u0, u1);
            upk(aR[i][p], r0, r1);
            const int j0 = 2 * p, j1 = 2 * p + 1;
            float v0 = (u0 + b2v[j0]) * gateR[i][j0] + r0 + brv[j0];
            float v1 = (u1 + b2v[j1]) * gateR[i][j1] + r1 + brv[j1];
            pv[j0] = v0; pv[j1] = v1;
            s  += v0 + v1;
            sq += v0 * v0 + v1 * v1;
        }
#pragma unroll
        for (int o = 1; o < 16; o <<= 1) {
            s  += __shfl_xor_sync(0xffffffffu, s, o);
            sq += __shfl_xor_sync(0xffffffffu, sq, o);
        }
        const float mu   = s * (1.f / 128.f);
        const float var  = sq * (1.f / 128.f) - mu * mu;
        const float rstd = rsqrtf(var + LN_EPS);
        if (e < E) {
            float o0 = (pv[0] - mu) * rstd * g2v[0] + be2v[0];
            float o1 = (pv[1] - mu) * rstd * g2v[1] + be2v[1];
            float o2 = (pv[2] - mu) * rstd * g2v[2] + be2v[2];
            float o3 = (pv[3] - mu) * rstd * g2v[3] + be2v[3];
            float o4 = (pv[4] - mu) * rstd * g2v[4] + be2v[4];
            float o5 = (pv[5] - mu) * rstd * g2v[5] + be2v[5];
            float o6 = (pv[6] - mu) * rstd * g2v[6] + be2v[6];
            float o7 = (pv[7] - mu) * rstd * g2v[7] + be2v[7];
            *(float4*)(out + (size_t)e * HID + 4 * tx)      = make_float4(o0, o1, o2, o3);
            *(float4*)(out + (size_t)e * HID + 64 + 4 * tx) = make_float4(o4, o5, o6, o7);
        }
    }
}

extern "C" void kernel_launch(void* const* d_in, const int* in_sizes, int n_in,
                              void* d_out, int out_size) {
    const float* x   = (const float*)d_in[0];
    const int*   ei  = (const int*)d_in[1];
    const float* ea  = (const float*)d_in[2];
    const float* W1  = (const float*)d_in[3];
    const float* b1  = (const float*)d_in[4];
    const float* g1  = (const float*)d_in[5];
    const float* be1 = (const float*)d_in[6];
    const float* W2  = (const float*)d_in[7];
    const float* b2  = (const float*)d_in[8];
    const float* Wg  = (const float*)d_in[9];
    const float* bg  = (const float*)d_in[10];
    const float* Wr  = (const float*)d_in[11];
    const float* br  = (const float*)d_in[12];
    const float* g2  = (const float*)d_in[13];
    const float* be2 = (const float*)d_in[14];

    const int E = in_sizes[2] / EDGED;
    const size_t smem = SMEM_FLOATS * sizeof(float);
    cudaFuncSetAttribute(edge_updater_kernel,
                         cudaFuncAttributeMaxDynamicSharedMemorySize, (int)smem);
    const int blocks = (E + EB - 1) / EB;
    edge_updater_kernel<<<blocks, 256, smem>>>(x, ei, ea, W1, b1, g1, be1, W2, b2,
                                               Wg, bg, Wr, br, g2, be2,
                                               (float*)d_out, E);
}

// round 7
// speedup vs baseline: 1.0997x; 1.0997x over previous
#include <cuda_runtime.h>
#include <math.h>
#include <stdint.h>

#define EB     64
#define PA     72     // sA/sH pitch (k-major), 72 % 32 == 8 -> conflict-free frags
#define PB1    264    // GEMM1 B chunk pitch
#define PB2    136    // GEMM2 B chunk pitch
#define PR     132    // row-major raw/gate/v pitch
#define LN_EPS 1e-5f

// shared float offsets
#define SM_A    0       // [320][72] cat_feat^T (tf32)   23040 floats
#define SM_B    23040   // weight double-buffer          16896 floats
#define SM_H    39936   // [128][72] h^T (tf32)           9216 floats
#define SM_BIAS 49152   // 8 x 128                        1024 floats
#define SM_TOT  50176   // 200704 bytes
#define SM_HRAW 0       // overlay on sA rows<256 after GEMM1: [64][132]
#define SM_G    8448    // gate [64][132]
#define SM_VRAW 0       // epilogue2 overlay [64][132]

__device__ __align__(16) float g_B1[320 * 256];  // [k][n] n<128:W1, else Wg (tf32)
__device__ __align__(16) float g_W2[128 * 128];  // [k][n] (tf32)
__device__ __align__(16) float g_Wr[64 * 128];   // [k][n] (tf32)

__device__ __forceinline__ float tf32r(float x) {
    float r; asm("cvt.rna.tf32.f32 %0, %1;" : "=f"(r) : "f"(x)); return r;
}
__device__ __forceinline__ uint32_t smem_u32(const void* p) {
    uint32_t a;
    asm("{ .reg .u64 t; cvta.to.shared.u64 t, %1; cvt.u32.u64 %0, t; }" : "=r"(a) : "l"(p));
    return a;
}
__device__ __forceinline__ void cpa16(uint32_t sa, const void* g) {
    asm volatile("cp.async.cg.shared.global [%0], [%1], 16;" :: "r"(sa), "l"(g));
}
__device__ __forceinline__ void cpa_commit() {
    asm volatile("cp.async.commit_group;" ::: "memory");
}
template <int N>
__device__ __forceinline__ void cpa_wait() {
    asm volatile("cp.async.wait_group %0;" :: "n"(N) : "memory");
}
// D = A(16x8,tf32) * B(8x8,tf32) + D, fp32 accum
__device__ __forceinline__ void mma8(float* c, const float* a, const float* b) {
    asm volatile(
        "mma.sync.aligned.m16n8k8.row.col.f32.tf32.tf32.f32 "
        "{%0,%1,%2,%3}, {%4,%5,%6,%7}, {%8,%9}, {%0,%1,%2,%3};"
        : "+f"(c[0]), "+f"(c[1]), "+f"(c[2]), "+f"(c[3])
        : "r"(__float_as_uint(a[0])), "r"(__float_as_uint(a[1])),
          "r"(__float_as_uint(a[2])), "r"(__float_as_uint(a[3])),
          "r"(__float_as_uint(b[0])), "r"(__float_as_uint(b[1])));
}

// ---------------- prep: tf32-round weights (all already k-major) ----------------
__global__ void prep_weights(const float* __restrict__ W1, const float* __restrict__ Wg,
                             const float* __restrict__ W2, const float* __restrict__ Wr) {
    int b = blockIdx.x, t = threadIdx.x;
    if (b < 320) {
        float v = (t < 128) ? W1[b * 128 + t] : Wg[b * 128 + (t - 128)];
        g_B1[b * 256 + t] = tf32r(v);
    } else if (b < 448) {
        if (t < 128) g_W2[(b - 320) * 128 + t] = tf32r(W2[(b - 320) * 128 + t]);
    } else {
        if (t < 128) g_Wr[(b - 448) * 128 + t] = tf32r(Wr[(b - 448) * 128 + t]);
    }
}

// ---------------- main fused kernel ----------------
__global__ __launch_bounds__(256, 1)
void edge_updater_mma(const float* __restrict__ x, const int* __restrict__ ei,
                      const float* __restrict__ ea,
                      const float* __restrict__ b1, const float* __restrict__ g1,
                      const float* __restrict__ be1, const float* __restrict__ b2,
                      const float* __restrict__ bg, const float* __restrict__ br,
                      const float* __restrict__ g2, const float* __restrict__ be2,
                      float* __restrict__ out, int E) {
    extern __shared__ float smem[];
    const uint32_t sbase = smem_u32(smem);
    const int tid  = threadIdx.x;
    const int lane = tid & 31;
    const int wid  = tid >> 5;
    const int wy   = wid & 1;   // M half (32 rows)
    const int wx   = wid >> 1;  // N quarter
    const int e0   = blockIdx.x * EB;

    float* sA = smem + SM_A;
    float* sH = smem + SM_H;
    float* sBias = smem + SM_BIAS;
    float* sHraw = smem + SM_HRAW;
    float* sG = smem + SM_G;
    float* sVraw = smem + SM_VRAW;

    // ---- async-prefetch GEMM1 B chunk 0 while gathering ----
    auto loadB1 = [&](int c) {
        const uint32_t sb = sbase + (SM_B + (c & 1) * 8448) * 4;
        const float* gsrc = g_B1 + c * 32 * 256;
#pragma unroll
        for (int i = 0; i < 8; i++) {
            int f = tid + i * 256;          // 2048 float4
            int kk = f >> 6, n4 = f & 63;
            cpa16(sb + (uint32_t)(kk * PB1 + n4 * 4) * 4, gsrc + kk * 256 + n4 * 4);
        }
    };
    auto loadB2 = [&](int j) {
        const uint32_t sb = sbase + (SM_B + (j & 1) * 4352) * 4;
#pragma unroll
        for (int i = 0; i < 4; i++) {
            int f = tid + i * 256;          // 1024 float4
            int kk = f >> 5, n4 = f & 31;
            const float* gsrc = (j < 4) ? (g_W2 + (j * 32 + kk) * 128 + n4 * 4)
                                        : (g_Wr + ((j - 4) * 32 + kk) * 128 + n4 * 4);
            cpa16(sb + (uint32_t)(kk * PB2 + n4 * 4) * 4, gsrc);
        }
    };

    loadB1(0); cpa_commit();

    // ---- gather cat_feat^T into sA (tf32-rounded) + biases ----
    {
        const int m = wid * 8 + (lane & 7);
        const int fb = lane >> 3;
        int e = e0 + m; if (e >= E) e = E - 1;
        const int src = ei[e], dst = ei[E + e];
        const float4* xs  = (const float4*)(x  + (size_t)src * 128);
        const float4* xd  = (const float4*)(x  + (size_t)dst * 128);
        const float4* eap = (const float4*)(ea + (size_t)e * 64);
#pragma unroll
        for (int f = fb; f < 80; f += 4) {
            float4 v;
            if (f < 32)      v = xs[f];
            else if (f < 64) v = xd[f - 32];
            else             v = eap[f - 64];
            const int k = f * 4;
            sA[(k + 0) * PA + m] = tf32r(v.x);
            sA[(k + 1) * PA + m] = tf32r(v.y);
            sA[(k + 2) * PA + m] = tf32r(v.z);
            sA[(k + 3) * PA + m] = tf32r(v.w);
        }
        if (tid < 128) {
            sBias[0 * 128 + tid] = b1[tid];
            sBias[1 * 128 + tid] = g1[tid];
            sBias[2 * 128 + tid] = be1[tid];
            sBias[3 * 128 + tid] = bg[tid];
            sBias[4 * 128 + tid] = b2[tid];
            sBias[5 * 128 + tid] = br[tid];
            sBias[6 * 128 + tid] = g2[tid];
            sBias[7 * 128 + tid] = be2[tid];
        }
    }

    // ---- GEMM1: C[64,256] = cat[64,320] @ B1[320,256], 10 k32 chunks ----
    float c1[2][8][4];
#pragma unroll
    for (int mi = 0; mi < 2; mi++)
#pragma unroll
        for (int ni = 0; ni < 8; ni++)
#pragma unroll
            for (int r = 0; r < 4; r++) c1[mi][ni][r] = 0.f;

    const int mrow = wy * 32 + (lane >> 2);
    const int klo  = lane & 3;
    const int nb1  = wx * 64 + (lane >> 2);

#pragma unroll 1
    for (int c = 0; c < 10; c++) {
        if (c < 9) { loadB1(c + 1); cpa_commit(); cpa_wait<1>(); }
        else cpa_wait<0>();
        __syncthreads();
        const float* Bb = smem + SM_B + (c & 1) * 8448;
#pragma unroll
        for (int kk = 0; kk < 4; kk++) {
            const int ka = c * 32 + kk * 8 + klo;   // abs k for A
            const int kb = kk * 8 + klo;            // chunk k for B
            float af[2][4];
#pragma unroll
            for (int mi = 0; mi < 2; mi++) {
                const float* Ap = sA + ka * PA + mrow + mi * 16;
                af[mi][0] = Ap[0];
                af[mi][1] = Ap[8];
                af[mi][2] = Ap[4 * PA];
                af[mi][3] = Ap[4 * PA + 8];
            }
#pragma unroll
            for (int ni = 0; ni < 8; ni++) {
                float bf[2];
                const float* Bp = Bb + kb * PB1 + nb1 + ni * 8;
                bf[0] = Bp[0];
                bf[1] = Bp[4 * PB1];
                mma8(c1[0][ni], af[0], bf);
                mma8(c1[1][ni], af[1], bf);
            }
        }
        __syncthreads();
    }

    // prefetch GEMM2 chunk 0 (sB free), overlap with epilogue 1
    loadB2(0); cpa_commit();

    // ---- epilogue 1a: scatter raw h (+b1) and sigmoid gate to smem ----
#pragma unroll
    for (int mi = 0; mi < 2; mi++)
#pragma unroll
        for (int ni = 0; ni < 8; ni++)
#pragma unroll
            for (int r = 0; r < 4; r++) {
                const int m = wy * 32 + mi * 16 + (lane >> 2) + (r >> 1) * 8;
                const int cn = wx * 64 + ni * 8 + 2 * (lane & 3) + (r & 1);
                float v = c1[mi][ni][r];
                if (cn < 128) {
                    sHraw[m * PR + cn] = v + sBias[cn];
                } else {
                    const int gn = cn - 128;
                    float gp = v + sBias[3 * 128 + gn];
                    sG[m * PR + gn] = 1.f / (1.f + __expf(-gp));
                }
            }
    __syncthreads();

    // ---- epilogue 1b: LN1 + GELU -> sH[k][m] (tf32) ----
    {
        const int r = tid >> 2, q = tid & 3;
        const float* row = sHraw + r * PR + q * 32;
        float hv[32];
        float s = 0.f, sq = 0.f;
#pragma unroll
        for (int i = 0; i < 32; i++) {
            hv[i] = row[i];
            s += hv[i]; sq += hv[i] * hv[i];
        }
        s  += __shfl_xor_sync(0xffffffffu, s, 1);
        sq += __shfl_xor_sync(0xffffffffu, sq, 1);
        s  += __shfl_xor_sync(0xffffffffu, s, 2);
        sq += __shfl_xor_sync(0xffffffffu, sq, 2);
        const float mu = s * (1.f / 128.f);
        const float var = sq * (1.f / 128.f) - mu * mu;
        const float rstd = rsqrtf(var + LN_EPS);
#pragma unroll
        for (int i = 0; i < 32; i++) {
            const int cn = q * 32 + i;
            float hn = (hv[i] - mu) * rstd * sBias[128 + cn] + sBias[256 + cn];
            float ge = 0.5f * hn * (1.f + erff(hn * 0.70710678118654752f));
            sH[cn * PA + r] = tf32r(ge);
        }
    }
    __syncthreads();

    // ---- GEMM2: update[64,128] = h @ W2 (j=0..3), res[64,128] = ea @ Wr (j=4..5) ----
    float cU[2][4][4], cR[2][4][4];
#pragma unroll
    for (int mi = 0; mi < 2; mi++)
#pragma unroll
        for (int ni = 0; ni < 4; ni++)
#pragma unroll
            for (int r = 0; r < 4; r++) { cU[mi][ni][r] = 0.f; cR[mi][ni][r] = 0.f; }

    const int nb2 = wx * 32 + (lane >> 2);

#pragma unroll 1
    for (int j = 0; j < 6; j++) {
        if (j < 5) { loadB2(j + 1); cpa_commit(); cpa_wait<1>(); }
        else cpa_wait<0>();
        __syncthreads();
        const float* Bb = smem + SM_B + (j & 1) * 4352;
        const float* Ab = (j < 4) ? (sH + (j * 32) * PA)
                                  : (sA + (256 + (j - 4) * 32) * PA);
        float (*acc)[4][4] = (j < 4) ? cU : cR;
#pragma unroll
        for (int kk = 0; kk < 4; kk++) {
            const int kc = kk * 8 + klo;
            float af[2][4];
#pragma unroll
            for (int mi = 0; mi < 2; mi++) {
                const float* Ap = Ab + kc * PA + mrow + mi * 16;
                af[mi][0] = Ap[0];
                af[mi][1] = Ap[8];
                af[mi][2] = Ap[4 * PA];
                af[mi][3] = Ap[4 * PA + 8];
            }
#pragma unroll
            for (int ni = 0; ni < 4; ni++) {
                float bf[2];
                const float* Bp = Bb + kc * PB2 + nb2 + ni * 8;
                bf[0] = Bp[0];
                bf[1] = Bp[4 * PB2];
                mma8(acc[0][ni], af[0], bf);
                mma8(acc[1][ni], af[1], bf);
            }
        }
        __syncthreads();
    }

    // ---- epilogue 2a: v = (update+b2)*gate + res + br -> sVraw ----
#pragma unroll
    for (int mi = 0; mi < 2; mi++)
#pragma unroll
        for (int ni = 0; ni < 4; ni++)
#pragma unroll
            for (int r = 0; r < 4; r++) {
                const int m = wy * 32 + mi * 16 + (lane >> 2) + (r >> 1) * 8;
                const int cn = wx * 32 + ni * 8 + 2 * (lane & 3) + (r & 1);
                float u = cU[mi][ni][r] + sBias[4 * 128 + cn];
                float rr = cR[mi][ni][r] + sBias[5 * 128 + cn];
                sVraw[m * PR + cn] = u * sG[m * PR + cn] + rr;
            }
    __syncthreads();

    // ---- epilogue 2b: LN2 + store ----
    {
        const int r = tid >> 2, q = tid & 3;
        const float* row = sVraw + r * PR + q * 32;
        float vv[32];
        float s = 0.f, sq = 0.f;
#pragma unroll
        for (int i = 0; i < 32; i++) {
            vv[i] = row[i];
            s += vv[i]; sq += vv[i] * vv[i];
        }
        s  += __shfl_xor_sync(0xffffffffu, s, 1);
        sq += __shfl_xor_sync(0xffffffffu, sq, 1);
        s  += __shfl_xor_sync(0xffffffffu, s, 2);
        sq += __shfl_xor_sync(0xffffffffu, sq, 2);
        const float mu = s * (1.f / 128.f);
        const float var = sq * (1.f / 128.f) - mu * mu;
        const float rstd = rsqrtf(var + LN_EPS);
        const int e = e0 + r;
        if (e < E) {
            float* op = out + (size_t)e * 128 + q * 32;
#pragma unroll
            for (int i4 = 0; i4 < 8; i4++) {
                float4 o;
#pragma unroll
                for (int u = 0; u < 4; u++) {
                    const int cn = q * 32 + i4 * 4 + u;
                    ((float*)&o)[u] = (vv[i4 * 4 + u] - mu) * rstd * sBias[6 * 128 + cn]
                                      + sBias[7 * 128 + cn];
                }
                *(float4*)(op + i4 * 4) = o;
            }
        }
    }
}

extern "C" void kernel_launch(void* const* d_in, const int* in_sizes, int n_in,
                              void* d_out, int out_size) {
    const float* x   = (const float*)d_in[0];
    const int*   ei  = (const int*)d_in[1];
    const float* ea  = (const float*)d_in[2];
    const float* W1  = (const float*)d_in[3];
    const float* b1  = (const float*)d_in[4];
    const float* g1  = (const float*)d_in[5];
    const float* be1 = (const float*)d_in[6];
    const float* W2  = (const float*)d_in[7];
    const float* b2  = (const float*)d_in[8];
    const float* Wg  = (const float*)d_in[9];
    const float* bg  = (const float*)d_in[10];
    const float* Wr  = (const float*)d_in[11];
    const float* br  = (const float*)d_in[12];
    const float* g2  = (const float*)d_in[13];
    const float* be2 = (const float*)d_in[14];

    const int E = in_sizes[1] / 2;

    prep_weights<<<512, 256>>>(W1, Wg, W2, Wr);

    const size_t smem = SM_TOT * sizeof(float);
    cudaFuncSetAttribute(edge_updater_mma,
                         cudaFuncAttributeMaxDynamicSharedMemorySize, (int)smem);
    const int blocks = (E + EB - 1) / EB;
    edge_updater_mma<<<blocks, 256, smem>>>(x, ei, ea, b1, g1, be1, b2, bg, br, g2, be2,
                                            (float*)d_out, E);
}

// round 8
// speedup vs baseline: 1.4755x; 1.3418x over previous
#include <cuda_runtime.h>
#include <math.h>
#include <stdint.h>

#define EB     128
#define PA     136    // A/H pitch ([k][m]); 136 % 32 == 8
#define PB1    264    // GEMM1 B pitch ([k][n])
#define PB2    136    // GEMM2 B pitch
#define LN_EPS 1e-5f

// ---- shared memory float offsets ----
#define O_BIAS 0        // 8 x 128: b1,g1,be1,bg,b2,br,g2,be2
#define O_SS   1024     // s partials [128][9]
#define O_SQ   2176     // sq partials [128][9]
#define O_MU   3328     // [128]
#define O_RS   3456     // [128]
#define O_EA   3584     // ea^T [64][136] = 8704
#define O_A0   12288    // A chunk buf0 [32][136] = 4352
#define O_A1   16640    // A chunk buf1
#define O_B1   20992    // 3 stages x (32x264=8448) -> end 46336
#define O_SH   12288    // overlay after GEMM1: h^T [128][136] = 17408 -> end 29696
#define O_B2   29696    // 3 stages x (32x136=4352) -> end 42752
#define O_TOT  46336    // 185344 bytes

// remapped tf32 weights:
// g_B1 col j: wn=j>>5, jj=j&31; jj<16 -> W1[:, 16*wn+jj], else Wg[:, 16*wn+jj-16]
__device__ __align__(16) float g_B1[320 * 256];
__device__ __align__(16) float g_W2[128 * 128];
__device__ __align__(16) float g_Wr[64 * 128];

__device__ __forceinline__ float tf32r(float x) {
    float r; asm("cvt.rna.tf32.f32 %0, %1;" : "=f"(r) : "f"(x)); return r;
}
__device__ __forceinline__ uint32_t smem_u32(const void* p) {
    uint32_t a;
    asm("{ .reg .u64 t; cvta.to.shared.u64 t, %1; cvt.u32.u64 %0, t; }" : "=r"(a) : "l"(p));
    return a;
}
__device__ __forceinline__ void cpa16(uint32_t sa, const void* g) {
    asm volatile("cp.async.cg.shared.global [%0], [%1], 16;" :: "r"(sa), "l"(g));
}
__device__ __forceinline__ void cpa_commit() {
    asm volatile("cp.async.commit_group;" ::: "memory");
}
template <int N>
__device__ __forceinline__ void cpa_wait() {
    asm volatile("cp.async.wait_group %0;" :: "n"(N) : "memory");
}
__device__ __forceinline__ void mma8(float* c, const float* a, const float* b) {
    asm volatile(
        "mma.sync.aligned.m16n8k8.row.col.f32.tf32.tf32.f32 "
        "{%0,%1,%2,%3}, {%4,%5,%6,%7}, {%8,%9}, {%0,%1,%2,%3};"
        : "+f"(c[0]), "+f"(c[1]), "+f"(c[2]), "+f"(c[3])
        : "r"(__float_as_uint(a[0])), "r"(__float_as_uint(a[1])),
          "r"(__float_as_uint(a[2])), "r"(__float_as_uint(a[3])),
          "r"(__float_as_uint(b[0])), "r"(__float_as_uint(b[1])));
}

__global__ void prep_weights(const float* __restrict__ W1, const float* __restrict__ Wg,
                             const float* __restrict__ W2, const float* __restrict__ Wr) {
    int b = blockIdx.x, t = threadIdx.x;
    if (b < 320) {
        int wn = t >> 5, jj = t & 31;
        float v = (jj < 16) ? W1[b * 128 + 16 * wn + jj]
                            : Wg[b * 128 + 16 * wn + jj - 16];
        g_B1[b * 256 + t] = tf32r(v);
    } else if (b < 448) {
        if (t < 128) g_W2[(b - 320) * 128 + t] = tf32r(W2[(b - 320) * 128 + t]);
    } else {
        if (t < 128) g_Wr[(b - 448) * 128 + t] = tf32r(Wr[(b - 448) * 128 + t]);
    }
}

__global__ __launch_bounds__(512)
void edge_updater_mma(const float* __restrict__ x, const int* __restrict__ ei,
                      const float* __restrict__ ea,
                      const float* __restrict__ b1, const float* __restrict__ g1,
                      const float* __restrict__ be1, const float* __restrict__ b2,
                      const float* __restrict__ bg, const float* __restrict__ br,
                      const float* __restrict__ g2, const float* __restrict__ be2,
                      float* __restrict__ out, int E) {
    extern __shared__ float smem[];
    const uint32_t sbase = smem_u32(smem);
    const int tid  = threadIdx.x;
    const int lane = tid & 31;
    const int lr   = lane >> 2;   // 0..7
    const int lc   = lane & 3;    // 0..3
    const int wid  = tid >> 5;
    const int wy   = wid & 1;     // M half (64 rows)
    const int wn   = wid >> 1;    // 0..7 N group (16 W1-cols + 16 Wg-cols)
    const int e0   = blockIdx.x * EB;

    // per-thread gather identity
    const int m_g  = tid & 127;
    const int kb_g = tid >> 7;    // 0..3
    int eg = e0 + m_g; if (eg >= E) eg = E - 1;
    const int idx_src = ei[eg];
    const int idx_dst = ei[E + eg];

    // ---- biases ----
    if (tid < 128) {
        smem[O_BIAS + 0   + tid] = b1[tid];
        smem[O_BIAS + 128 + tid] = g1[tid];
        smem[O_BIAS + 256 + tid] = be1[tid];
        smem[O_BIAS + 384 + tid] = bg[tid];
        smem[O_BIAS + 512 + tid] = b2[tid];
        smem[O_BIAS + 640 + tid] = br[tid];
        smem[O_BIAS + 768 + tid] = g2[tid];
        smem[O_BIAS + 896 + tid] = be2[tid];
    }

    // ---- B1 stages 0,1 via cp.async ----
    auto loadB1 = [&](int c) {
        const uint32_t sb = sbase + (O_B1 + (c % 3) * 8448) * 4;
        const float* gsrc = g_B1 + (size_t)c * 32 * 256;
#pragma unroll
        for (int i = 0; i < 4; i++) {
            int f = tid + i * 512;            // 2048 float4
            int kk = f >> 6, n4 = f & 63;
            cpa16(sb + (uint32_t)(kk * PB1 + n4 * 4) * 4, gsrc + kk * 256 + n4 * 4);
        }
    };
    auto loadB2 = [&](int j) {
        const uint32_t sb = sbase + (O_B2 + (j % 3) * 4352) * 4;
#pragma unroll
        for (int i = 0; i < 2; i++) {
            int f = tid + i * 512;            // 1024 float4
            int kk = f >> 5, n4 = f & 31;
            const float* gsrc = (j < 4) ? (g_W2 + (j * 32 + kk) * 128 + n4 * 4)
                                        : (g_Wr + ((j - 4) * 32 + kk) * 128 + n4 * 4);
            cpa16(sb + (uint32_t)(kk * PB2 + n4 * 4) * 4, gsrc);
        }
    };

    loadB1(0); cpa_commit();
    loadB1(1); cpa_commit();

    // ---- ea^T gather [64 k][136 m] ----
    {
        const float4* src = (const float4*)(ea + (size_t)eg * 64);
#pragma unroll
        for (int i = 0; i < 4; i++) {
            int k0 = kb_g * 16 + i * 4;
            float4 v = src[k0 >> 2];
            smem[O_EA + (k0 + 0) * PA + m_g] = tf32r(v.x);
            smem[O_EA + (k0 + 1) * PA + m_g] = tf32r(v.y);
            smem[O_EA + (k0 + 2) * PA + m_g] = tf32r(v.z);
            smem[O_EA + (k0 + 3) * PA + m_g] = tf32r(v.w);
        }
    }

    // A gather helpers (chunks 0..7 come from x; 8,9 from ea region)
    auto ldA = [&](int c, float4& r0, float4& r1) {
        const int idx = (c < 4) ? idx_src : idx_dst;
        const float* p = x + (size_t)idx * 128 + (c & 3) * 32 + kb_g * 8;
        r0 = *(const float4*)p;
        r1 = *(const float4*)(p + 4);
    };
    auto stA = [&](int c, const float4& r0, const float4& r1) {
        float* dst = smem + ((c & 1) ? O_A1 : O_A0);
        const int k0 = kb_g * 8;
        dst[(k0 + 0) * PA + m_g] = tf32r(r0.x);
        dst[(k0 + 1) * PA + m_g] = tf32r(r0.y);
        dst[(k0 + 2) * PA + m_g] = tf32r(r0.z);
        dst[(k0 + 3) * PA + m_g] = tf32r(r0.w);
        dst[(k0 + 4) * PA + m_g] = tf32r(r1.x);
        dst[(k0 + 5) * PA + m_g] = tf32r(r1.y);
        dst[(k0 + 6) * PA + m_g] = tf32r(r1.z);
        dst[(k0 + 7) * PA + m_g] = tf32r(r1.w);
    };

    {
        float4 a0, a1;
        ldA(0, a0, a1);
        stA(0, a0, a1);
    }

    // ---- GEMM1: C[128,256] = cat[128,320] @ B1, 10 k32 chunks ----
    float c1[4][4][4];
#pragma unroll
    for (int mi = 0; mi < 4; mi++)
#pragma unroll
        for (int ni = 0; ni < 4; ni++)
#pragma unroll
            for (int r = 0; r < 4; r++) c1[mi][ni][r] = 0.f;

#pragma unroll 1
    for (int c = 0; c < 10; c++) {
        float4 a0, a1;
        if (c + 1 < 8) ldA(c + 1, a0, a1);
        if (c < 9) cpa_wait<1>(); else cpa_wait<0>();
        __syncthreads();
        if (c + 2 < 10) { loadB1(c + 2); cpa_commit(); }

        const float* Ab = (c < 8) ? (smem + ((c & 1) ? O_A1 : O_A0))
                                  : (smem + O_EA + (c - 8) * 32 * PA);
        const float* Bb = smem + O_B1 + (c % 3) * 8448;
#pragma unroll
        for (int kk = 0; kk < 4; kk++) {
            const float* Ap = Ab + (kk * 8 + lc) * PA + wy * 64 + lr;
            float af[4][4];
#pragma unroll
            for (int mi = 0; mi < 4; mi++) {
                af[mi][0] = Ap[mi * 16];
                af[mi][1] = Ap[mi * 16 + 8];
                af[mi][2] = Ap[4 * PA + mi * 16];
                af[mi][3] = Ap[4 * PA + mi * 16 + 8];
            }
#pragma unroll
            for (int ni = 0; ni < 4; ni++) {
                const float* Bp = Bb + (kk * 8 + lc) * PB1 + wn * 32 + ni * 8 + lr;
                float bf[2] = { Bp[0], Bp[4 * PB1] };
#pragma unroll
                for (int mi = 0; mi < 4; mi++) mma8(c1[mi][ni], af[mi], bf);
            }
        }
        if (c + 1 < 8) stA(c + 1, a0, a1);
    }

    // prefetch GEMM2 B stages 0,1 (regions safe: all warps past chunk-9 sync)
    loadB2(0); cpa_commit();
    loadB2(1); cpa_commit();

    // ---- epilogue 1: +b1, LN1 partials, GELU -> sH; gate -> regs ----
    float sl[4][2], ql[4][2];
#pragma unroll
    for (int mi = 0; mi < 4; mi++)
#pragma unroll
        for (int rh = 0; rh < 2; rh++) {
            float s = 0.f, q = 0.f;
#pragma unroll
            for (int ni = 0; ni < 2; ni++)
#pragma unroll
                for (int rl = 0; rl < 2; rl++) {
                    const int n = 16 * wn + ni * 8 + 2 * lc + rl;
                    float v = c1[mi][ni][2 * rh + rl] + smem[O_BIAS + n];
                    c1[mi][ni][2 * rh + rl] = v;
                    s += v; q += v * v;
                }
            s += __shfl_xor_sync(0xffffffffu, s, 1);
            q += __shfl_xor_sync(0xffffffffu, q, 1);
            s += __shfl_xor_sync(0xffffffffu, s, 2);
            q += __shfl_xor_sync(0xffffffffu, q, 2);
            sl[mi][rh] = s; ql[mi][rh] = q;
        }
    if (lc == 0) {
#pragma unroll
        for (int mi = 0; mi < 4; mi++)
#pragma unroll
            for (int rh = 0; rh < 2; rh++) {
                const int m = wy * 64 + mi * 16 + lr + 8 * rh;
                smem[O_SS + m * 9 + wn] = sl[mi][rh];
                smem[O_SQ + m * 9 + wn] = ql[mi][rh];
            }
    }
    __syncthreads();
    if (tid < 128) {
        float s = 0.f, q = 0.f;
#pragma unroll
        for (int i = 0; i < 8; i++) {
            s += smem[O_SS + tid * 9 + i];
            q += smem[O_SQ + tid * 9 + i];
        }
        const float mu = s * (1.f / 128.f);
        const float var = q * (1.f / 128.f) - mu * mu;
        smem[O_MU + tid] = mu;
        smem[O_RS + tid] = rsqrtf(var + LN_EPS);
    }
    __syncthreads();

    float gate[4][2][4];
#pragma unroll
    for (int mi = 0; mi < 4; mi++)
#pragma unroll
        for (int rh = 0; rh < 2; rh++) {
            const int m = wy * 64 + mi * 16 + lr + 8 * rh;
            const float mu = smem[O_MU + m];
            const float rs = smem[O_RS + m];
#pragma unroll
            for (int ni = 0; ni < 2; ni++)
#pragma unroll
                for (int rl = 0; rl < 2; rl++) {
                    const int n = 16 * wn + ni * 8 + 2 * lc + rl;
                    float hv = (c1[mi][ni][2 * rh + rl] - mu) * rs
                               * smem[O_BIAS + 128 + n] + smem[O_BIAS + 256 + n];
                    float ge = 0.5f * hv * (1.f + erff(hv * 0.70710678118654752f));
                    smem[O_SH + n * PA + m] = tf32r(ge);
                    // gate (ni2 = ni): preact in c1[mi][2+ni]
                    const float gp = c1[mi][2 + ni][2 * rh + rl] + smem[O_BIAS + 384 + n];
                    gate[mi][ni][2 * rh + rl] = 1.f / (1.f + __expf(-gp));
                }
        }

    // ---- GEMM2: update = h @ W2 (j 0..3), res = ea @ Wr (j 4..5) ----
    float cU[4][2][4], cR[4][2][4];
#pragma unroll
    for (int mi = 0; mi < 4; mi++)
#pragma unroll
        for (int ni = 0; ni < 2; ni++)
#pragma unroll
            for (int r = 0; r < 4; r++) { cU[mi][ni][r] = 0.f; cR[mi][ni][r] = 0.f; }

#pragma unroll 1
    for (int j = 0; j < 6; j++) {
        if (j < 5) cpa_wait<1>(); else cpa_wait<0>();
        __syncthreads();
        if (j + 2 < 6) { loadB2(j + 2); cpa_commit(); }

        const float* Ab = (j < 4) ? (smem + O_SH + j * 32 * PA)
                                  : (smem + O_EA + (j - 4) * 32 * PA);
        const float* Bb = smem + O_B2 + (j % 3) * 4352;
        float (*acc)[2][4] = (j < 4) ? cU : cR;
#pragma unroll
        for (int kk = 0; kk < 4; kk++) {
            const float* Ap = Ab + (kk * 8 + lc) * PA + wy * 64 + lr;
            float af[4][4];
#pragma unroll
            for (int mi = 0; mi < 4; mi++) {
                af[mi][0] = Ap[mi * 16];
                af[mi][1] = Ap[mi * 16 + 8];
                af[mi][2] = Ap[4 * PA + mi * 16];
                af[mi][3] = Ap[4 * PA + mi * 16 + 8];
            }
#pragma unroll
            for (int ni = 0; ni < 2; ni++) {
                const float* Bp = Bb + (kk * 8 + lc) * PB2 + wn * 16 + ni * 8 + lr;
                float bf[2] = { Bp[0], Bp[4 * PB2] };
#pragma unroll
                for (int mi = 0; mi < 4; mi++) mma8(acc[mi][ni], af[mi], bf);
            }
        }
    }

    // ---- epilogue 2: v = (update+b2)*gate + res + br; LN2; store ----
#pragma unroll
    for (int mi = 0; mi < 4; mi++)
#pragma unroll
        for (int rh = 0; rh < 2; rh++) {
            float s = 0.f, q = 0.f;
#pragma unroll
            for (int ni = 0; ni < 2; ni++)
#pragma unroll
                for (int rl = 0; rl < 2; rl++) {
                    const int n = 16 * wn + ni * 8 + 2 * lc + rl;
                    const int r = 2 * rh + rl;
                    float v = (cU[mi][ni][r] + smem[O_BIAS + 512 + n]) * gate[mi][ni][r]
                              + cR[mi][ni][r] + smem[O_BIAS + 640 + n];
                    cU[mi][ni][r] = v;
                    s += v; q += v * v;
                }
            s += __shfl_xor_sync(0xffffffffu, s, 1);
            q += __shfl_xor_sync(0xffffffffu, q, 1);
            s += __shfl_xor_sync(0xffffffffu, s, 2);
            q += __shfl_xor_sync(0xffffffffu, q, 2);
            sl[mi][rh] = s; ql[mi][rh] = q;
        }
    __syncthreads();   // all LN1 stat reads done before overwrite
    if (lc == 0) {
#pragma unroll
        for (int mi = 0; mi < 4; mi++)
#pragma unroll
            for (int rh = 0; rh < 2; rh++) {
                const int m = wy * 64 + mi * 16 + lr + 8 * rh;
                smem[O_SS + m * 9 + wn] = sl[mi][rh];
                smem[O_SQ + m * 9 + wn] = ql[mi][rh];
            }
    }
    __syncthreads();
    if (tid < 128) {
        float s = 0.f, q = 0.f;
#pragma unroll
        for (int i = 0; i < 8; i++) {
            s += smem[O_SS + tid * 9 + i];
            q += smem[O_SQ + tid * 9 + i];
        }
        const float mu = s * (1.f / 128.f);
        const float var = q * (1.f / 128.f) - mu * mu;
        smem[O_MU + tid] = mu;
        smem[O_RS + tid] = rsqrtf(var + LN_EPS);
    }
    __syncthreads();

#pragma unroll
    for (int mi = 0; mi < 4; mi++)
#pragma unroll
        for (int rh = 0; rh < 2; rh++) {
            const int m = wy * 64 + mi * 16 + lr + 8 * rh;
            const int e = e0 + m;
            if (e < E) {
                const float mu = smem[O_MU + m];
                const float rs = smem[O_RS + m];
#pragma unroll
                for (int ni = 0; ni < 2; ni++) {
                    const int n0 = 16 * wn + ni * 8 + 2 * lc;
                    float2 o;
                    o.x = (cU[mi][ni][2 * rh + 0] - mu) * rs
                          * smem[O_BIAS + 768 + n0] + smem[O_BIAS + 896 + n0];
                    o.y = (cU[mi][ni][2 * rh + 1] - mu) * rs
                          * smem[O_BIAS + 768 + n0 + 1] + smem[O_BIAS + 896 + n0 + 1];
                    *(float2*)(out + (size_t)e * 128 + n0) = o;
                }
            }
        }
}

extern "C" void kernel_launch(void* const* d_in, const int* in_sizes, int n_in,
                              void* d_out, int out_size) {
    const float* x   = (const float*)d_in[0];
    const int*   ei  = (const int*)d_in[1];
    const float* ea  = (const float*)d_in[2];
    const float* W1  = (const float*)d_in[3];
    const float* b1  = (const float*)d_in[4];
    const float* g1  = (const float*)d_in[5];
    const float* be1 = (const float*)d_in[6];
    const float* W2  = (const float*)d_in[7];
    const float* b2  = (const float*)d_in[8];
    const float* Wg  = (const float*)d_in[9];
    const float* bg  = (const float*)d_in[10];
    const float* Wr  = (const float*)d_in[11];
    const float* br  = (const float*)d_in[12];
    const float* g2  = (const float*)d_in[13];
    const float* be2 = (const float*)d_in[14];

    const int E = in_sizes[1] / 2;

    prep_weights<<<512, 256>>>(W1, Wg, W2, Wr);

    const size_t smem = O_TOT * sizeof(float);
    cudaFuncSetAttribute(edge_updater_mma,
                         cudaFuncAttributeMaxDynamicSharedMemorySize, (int)smem);
    const int blocks = (E + EB - 1) / EB;
    edge_updater_mma<<<blocks, 512, smem>>>(x, ei, ea, b1, g1, be1, b2, bg, br, g2, be2,
                                            (float*)d_out, E);
}